// round 13
// baseline (speedup 1.0000x reference)
#include <cuda_runtime.h>
#include <float.h>

// ChessMoveSelector — algebraically collapsed.  FINAL (= round-8 measured best).
//
// probs[b,n] = mask * softmax_n( moves[b,n,0]*w0 + moves[b,n,1]*w1 )
// where w = move_w^T @ comb_w[0, BD:].  All batch-constant terms (the entire
// conv1->conv2->fc->extra board branch, all biases) cancel inside the row
// softmax, so the 19-GFLOP network reduces to a 2-element dot product per
// move + a masked 64-wide softmax.  Traffic: 3 MB total.
//
// Measured design space (kernel time):
//   512thr x 256CTA, 1 row/warp:            4.896 us  <- optimum (this file)
//   128thr x 1024CTA:                       5.088 us
//   1024thr x 128CTA:                       5.088 us
//   2 rows/warp (MLP=2, 2048 warps):        5.056 us
//   CTA-shared w via smem + barrier:        5.088 us
// Remaining time = launch/ramp overhead (~5000 cyc) + one exposed DRAM
// latency; the warp tail (reductions, exp, stores) is fully hidden.

#define NMAX 64
#define MD 128
#define BD 256

// Order-preserving float <-> int monotone mapping for integer max reduction.
__device__ __forceinline__ int f32_to_ordered_s32(float f) {
    int i = __float_as_int(f);
    return (i < 0) ? (i ^ 0x7fffffff) : i;   // now s32 compare == fp32 compare
}

__device__ __forceinline__ float warp_max_f32(float v) {
    int key = f32_to_ordered_s32(v);
    int r;
    asm volatile("redux.sync.max.s32 %0, %1, 0xffffffff;" : "=r"(r) : "r"(key));
    r = (r < 0) ? (r ^ 0x7fffffff) : r;      // invert mapping
    return __int_as_float(r);
}

__device__ __forceinline__ int warp_sum_s32(int v) {
    int r;
    asm volatile("redux.sync.add.s32 %0, %1, 0xffffffff;" : "=r"(r) : "r"(v));
    return r;
}

__global__ void __launch_bounds__(512)
chess_move_softmax_kernel(
    const float4* __restrict__ moves4,  // [B*32] float4 == [B,64,2] floats
    const int*    __restrict__ lengths, // [B]
    const float2* __restrict__ move_w2, // [128] float2 == move_w[128,2]
    const float*  __restrict__ comb_w,  // [384]
    float2*       __restrict__ out2,    // [B*32] float2 == probs[B,64]
    int B)
{
    const int warp = (blockIdx.x * blockDim.x + threadIdx.x) >> 5;
    const int lane = threadIdx.x & 31;
    if (warp >= B) return;

    // ---- Issue ALL global loads up front so DRAM latencies overlap ----
    const int    len = lengths[warp];
    const float4 mv  = __ldcs(&moves4[(size_t)warp * 32 + lane]);  // read-once

    float cw[4];
    float2 mw[4];
    #pragma unroll
    for (int i = 0; i < 4; i++) {
        const int m = lane + i * 32;
        cw[i] = comb_w[BD + m];
        mw[i] = move_w2[m];
    }

    // ---- Per-warp collapsed weight vector w = move_w^T @ comb_w[BD:] ----
    // (hidden under the in-flight moves DRAM load)
    float s0 = 0.f, s1 = 0.f;
    #pragma unroll
    for (int i = 0; i < 4; i++) {
        s0 = fmaf(cw[i], mw[i].x, s0);
        s1 = fmaf(cw[i], mw[i].y, s1);
    }
    #pragma unroll
    for (int off = 16; off > 0; off >>= 1) {
        s0 += __shfl_xor_sync(0xffffffffu, s0, off);
        s1 += __shfl_xor_sync(0xffffffffu, s1, off);
    }
    const float w0 = s0;
    const float w1 = s1;

    // ---- Scores for this lane's 2 moves ----
    const int  n0 = 2 * lane;
    const bool v0 = (n0     < len);
    const bool v1 = (n0 + 1 < len);

    const float sc0 = fmaf(mv.x, w0, mv.y * w1);
    const float sc1 = fmaf(mv.z, w0, mv.w * w1);

    // ---- Masked softmax over the 64 moves of this row ----
    const float mx = warp_max_f32(fmaxf(v0 ? sc0 : -FLT_MAX,
                                        v1 ? sc1 : -FLT_MAX));

    const float e0 = v0 ? __expf(sc0 - mx) : 0.f;   // in (0, 1]
    const float e1 = v1 ? __expf(sc1 - mx) : 0.f;

    // Fixed-point warp sum: e in [0,1], scale 2^24, sum <= 64*2^24 = 2^30.
    const int q = __float2int_rn(e0 * 16777216.0f)
                + __float2int_rn(e1 * 16777216.0f);
    const float sumf = (float)warp_sum_s32(q);      // = sum * 2^24 (quantized)
    const float inv  = __fdividef(16777216.0f, sumf);

    float2 r;
    r.x = e0 * inv;
    r.y = e1 * inv;
    __stcs(&out2[(size_t)warp * 32 + lane], r);     // write-once: streaming store
}

extern "C" void kernel_launch(void* const* d_in, const int* in_sizes, int n_in,
                              void* d_out, int out_size)
{
    const float4* moves   = (const float4*)d_in[2];
    const int*    lengths = (const int*)d_in[3];
    const float2* move_w  = (const float2*)d_in[12];
    const float*  comb_w  = (const float*)d_in[14];
    float2* out = (float2*)d_out;

    const int B = in_sizes[3];                 // 4096 rows
    const int threads = 512;                   // 16 warps -> 16 rows per block
    const int warps_per_block = threads / 32;
    const int blocks = (B + warps_per_block - 1) / warps_per_block;  // 256

    chess_move_softmax_kernel<<<blocks, threads>>>(moves, lengths, move_w, comb_w, out, B);
}

// round 15
// speedup vs baseline: 1.1148x; 1.1148x over previous
#include <cuda_runtime.h>
#include <float.h>

// ChessMoveSelector — algebraically collapsed.
//
// probs[b,n] = mask * softmax_n( moves[b,n,0]*w0 + moves[b,n,1]*w1 )
// where w = move_w^T @ comb_w[0, BD:].  All batch-constant terms (the entire
// conv1->conv2->fc->extra board branch, all biases) cancel inside the row
// softmax, so the 19-GFLOP network reduces to a 2-element dot product per
// move + a masked 64-wide softmax.  Traffic: 3 MB total.
//
// Round 15 (= Round 14 resubmit after infra failure): round-8 consensus body
// at the best-measured shape (512thr x 256CTA, 1 row/warp), with __ldcs
// REMOVED from the moves load: during the timed graph-replay loop the 2MB
// input is L2-resident, and evict-first hints were ejecting it between
// replays (forcing 577-cyc DRAM instead of ~250-cyc L2 hits).  ncu can't
// show this (its --cache-control all flushes caches).  Output keeps the
// streaming store (write-once per replay; keeps L2 clean for the input).
//
// Measured context: identical source drew 4.896us (R8) and 5.856us (R13) —
// run-to-run clock variance ~±0.5us dominates all structural deltas.

#define NMAX 64
#define MD 128
#define BD 256

// Order-preserving float <-> int monotone mapping for integer max reduction.
__device__ __forceinline__ int f32_to_ordered_s32(float f) {
    int i = __float_as_int(f);
    return (i < 0) ? (i ^ 0x7fffffff) : i;   // now s32 compare == fp32 compare
}

__device__ __forceinline__ float warp_max_f32(float v) {
    int key = f32_to_ordered_s32(v);
    int r;
    asm volatile("redux.sync.max.s32 %0, %1, 0xffffffff;" : "=r"(r) : "r"(key));
    r = (r < 0) ? (r ^ 0x7fffffff) : r;      // invert mapping
    return __int_as_float(r);
}

__device__ __forceinline__ int warp_sum_s32(int v) {
    int r;
    asm volatile("redux.sync.add.s32 %0, %1, 0xffffffff;" : "=r"(r) : "r"(v));
    return r;
}

__global__ void __launch_bounds__(512)
chess_move_softmax_kernel(
    const float4* __restrict__ moves4,  // [B*32] float4 == [B,64,2] floats
    const int*    __restrict__ lengths, // [B]
    const float2* __restrict__ move_w2, // [128] float2 == move_w[128,2]
    const float*  __restrict__ comb_w,  // [384]
    float2*       __restrict__ out2,    // [B*32] float2 == probs[B,64]
    int B)
{
    const int warp = (blockIdx.x * blockDim.x + threadIdx.x) >> 5;
    const int lane = threadIdx.x & 31;
    if (warp >= B) return;

    // ---- Issue ALL global loads up front so their latencies overlap ----
    // Default cache policy: moves stays L2-resident across graph replays.
    const int    len = lengths[warp];
    const float4 mv  = moves4[(size_t)warp * 32 + lane];

    float cw[4];
    float2 mw[4];
    #pragma unroll
    for (int i = 0; i < 4; i++) {
        const int m = lane + i * 32;
        cw[i] = comb_w[BD + m];
        mw[i] = move_w2[m];
    }

    // ---- Per-warp collapsed weight vector w = move_w^T @ comb_w[BD:] ----
    // (hidden under the in-flight moves load)
    float s0 = 0.f, s1 = 0.f;
    #pragma unroll
    for (int i = 0; i < 4; i++) {
        s0 = fmaf(cw[i], mw[i].x, s0);
        s1 = fmaf(cw[i], mw[i].y, s1);
    }
    #pragma unroll
    for (int off = 16; off > 0; off >>= 1) {
        s0 += __shfl_xor_sync(0xffffffffu, s0, off);
        s1 += __shfl_xor_sync(0xffffffffu, s1, off);
    }
    const float w0 = s0;
    const float w1 = s1;

    // ---- Scores for this lane's 2 moves ----
    const int  n0 = 2 * lane;
    const bool v0 = (n0     < len);
    const bool v1 = (n0 + 1 < len);

    const float sc0 = fmaf(mv.x, w0, mv.y * w1);
    const float sc1 = fmaf(mv.z, w0, mv.w * w1);

    // ---- Masked softmax over the 64 moves of this row ----
    const float mx = warp_max_f32(fmaxf(v0 ? sc0 : -FLT_MAX,
                                        v1 ? sc1 : -FLT_MAX));

    const float e0 = v0 ? __expf(sc0 - mx) : 0.f;   // in (0, 1]
    const float e1 = v1 ? __expf(sc1 - mx) : 0.f;

    // Fixed-point warp sum: e in [0,1], scale 2^24, sum <= 64*2^24 = 2^30.
    const int q = __float2int_rn(e0 * 16777216.0f)
                + __float2int_rn(e1 * 16777216.0f);
    const float sumf = (float)warp_sum_s32(q);      // = sum * 2^24 (quantized)
    const float inv  = __fdividef(16777216.0f, sumf);

    float2 r;
    r.x = e0 * inv;
    r.y = e1 * inv;
    __stcs(&out2[(size_t)warp * 32 + lane], r);     // write-once: streaming store
}

extern "C" void kernel_launch(void* const* d_in, const int* in_sizes, int n_in,
                              void* d_out, int out_size)
{
    const float4* moves   = (const float4*)d_in[2];
    const int*    lengths = (const int*)d_in[3];
    const float2* move_w  = (const float2*)d_in[12];
    const float*  comb_w  = (const float*)d_in[14];
    float2* out = (float2*)d_out;

    const int B = in_sizes[3];                 // 4096 rows
    const int threads = 512;                   // 16 warps -> 16 rows per block
    const int warps_per_block = threads / 32;
    const int blocks = (B + warps_per_block - 1) / warps_per_block;  // 256

    chess_move_softmax_kernel<<<blocks, threads>>>(moves, lengths, move_w, comb_w, out, B);
}